// round 1
// baseline (speedup 1.0000x reference)
#include <cuda_runtime.h>

#define B 256
#define D 128
#define NEG 1024
#define SAMPLES 300000
#define TEMPR 0.07f
#define EPS 1e-12f

// scratch for normalized embeddings (allocation-free rule: __device__ globals)
__device__ __align__(16) float g_na[B * D];
__device__ __align__(16) float g_nv[B * D];

__device__ __forceinline__ float warp_sum(float v) {
#pragma unroll
    for (int o = 16; o; o >>= 1) v += __shfl_down_sync(0xffffffffu, v, o);
    return v;
}

// 128-thread block sum, broadcast to all threads
__device__ __forceinline__ float block_sum128(float v, float* sm) {
    int lane = threadIdx.x & 31, w = threadIdx.x >> 5;
    float s = warp_sum(v);
    if (lane == 0) sm[w] = s;
    __syncthreads();
    float r = sm[0] + sm[1] + sm[2] + sm[3];
    __syncthreads();
    return r;
}

// Detect whether an index buffer is int64 or int32 (JAX x64 demotion hedge).
// Values are random in [0, 300000): if int64, the odd 32-bit words (hi words)
// of the first 4 elements are all zero; if int32, they are 4 random nonzero ints.
__device__ __forceinline__ bool is_i64(const void* p) {
    const int* q = (const int*)p;
    return ((q[1] | q[3] | q[5] | q[7]) == 0);
}

__device__ __forceinline__ long long ld_idx(const void* p, long long i, bool is64) {
    return is64 ? ((const long long*)p)[i] : (long long)((const int*)p)[i];
}

// One block per batch row b, 128 threads (one per dim).
// Computes na/nv, positive scores, and the momentum-updated rows scattered
// into the already-copied output memories.
__global__ void prep_kernel(const float* __restrict__ audio_emb,
                            const float* __restrict__ video_emb,
                            const float* __restrict__ amem,
                            const float* __restrict__ vmem,
                            const void* __restrict__ indices,
                            float* __restrict__ out_scores,
                            float* __restrict__ out_amem,
                            float* __restrict__ out_vmem) {
    __shared__ float sm[4];
    const int b = blockIdx.x, t = threadIdx.x;
    const bool is64 = is_i64(indices);

    float a = audio_emb[b * D + t];
    float v = video_emb[b * D + t];
    float sa = block_sum128(a * a, sm);
    float sv = block_sum128(v * v, sm);
    float na = a / fmaxf(sqrtf(sa), EPS);
    float nv = v / fmaxf(sqrtf(sv), EPS);
    g_na[b * D + t] = na;
    g_nv[b * D + t] = nv;

    long long idx = ld_idx(indices, b, is64);
    float pa = amem[idx * D + t];
    float pv = vmem[idx * D + t];

    float d_apv = block_sum128(na * pv, sm);
    float d_vpa = block_sum128(nv * pa, sm);
    float d_apa = block_sum128(na * pa, sm);
    float d_vpv = block_sum128(nv * pv, sm);
    if (t == 0) {
        const long long S = (long long)B * (1 + NEG);
        out_scores[0 * S + (long long)b * (1 + NEG)] = d_apv / TEMPR;
        out_scores[1 * S + (long long)b * (1 + NEG)] = d_vpa / TEMPR;
        out_scores[2 * S + (long long)b * (1 + NEG)] = d_apa / TEMPR;
        out_scores[3 * S + (long long)b * (1 + NEG)] = d_vpv / TEMPR;
    }

    // momentum update: l2n(pos*0.5 + n*0.5), scatter into output copies
    float ma = pa * 0.5f + na * 0.5f;
    float mv = pv * 0.5f + nv * 0.5f;
    float sma = block_sum128(ma * ma, sm);
    float smv = block_sum128(mv * mv, sm);
    out_amem[idx * D + t] = ma / fmaxf(sqrtf(sma), EPS);
    out_vmem[idx * D + t] = mv / fmaxf(sqrtf(smv), EPS);
}

// grid (B, 2), 512 threads = 16 warps. Each block handles 512 negatives of
// one batch row. Warp-per-negative: each lane holds float4 slices of na/nv
// (fixed per lane), loads float4 slices of the gathered neg rows, computes
// all 4 dot products, shuffle-reduces, stages in smem, coalesced write.
__global__ __launch_bounds__(512) void score_kernel(
    const float* __restrict__ amem, const float* __restrict__ vmem,
    const void* __restrict__ indices, const void* __restrict__ negs,
    float* __restrict__ out_scores) {
    const int b = blockIdx.x;
    const int n0 = blockIdx.y * 512;
    const int lane = threadIdx.x & 31;
    const int w = threadIdx.x >> 5;
    const bool is64i = is_i64(indices);
    const bool is64n = is_i64(negs);

    const float4 na4 = *(const float4*)(g_na + b * D + lane * 4);
    const float4 nv4 = *(const float4*)(g_nv + b * D + lane * 4);
    const long long idx = ld_idx(indices, b, is64i);

    __shared__ float sbuf[4][512];

#pragma unroll 2
    for (int i = w; i < 512; i += 16) {
        long long neg = ld_idx(negs, (long long)b * NEG + n0 + i, is64n);
        long long row = neg + (neg >= idx ? 1 : 0);
        const float4 av = *(const float4*)(amem + row * D + lane * 4);
        const float4 vv = *(const float4*)(vmem + row * D + lane * 4);

        float s_aa = av.x * na4.x + av.y * na4.y + av.z * na4.z + av.w * na4.w;
        float s_av = av.x * nv4.x + av.y * nv4.y + av.z * nv4.z + av.w * nv4.w;
        float s_va = vv.x * na4.x + vv.y * na4.y + vv.z * na4.z + vv.w * na4.w;
        float s_vv = vv.x * nv4.x + vv.y * nv4.y + vv.z * nv4.z + vv.w * nv4.w;

#pragma unroll
        for (int o = 16; o; o >>= 1) {
            s_aa += __shfl_down_sync(0xffffffffu, s_aa, o);
            s_av += __shfl_down_sync(0xffffffffu, s_av, o);
            s_va += __shfl_down_sync(0xffffffffu, s_va, o);
            s_vv += __shfl_down_sync(0xffffffffu, s_vv, o);
        }
        if (lane == 0) {
            // score order: [0]=neg_v·na  [1]=neg_a·nv  [2]=neg_a·na  [3]=neg_v·nv
            sbuf[0][i] = s_va;
            sbuf[1][i] = s_av;
            sbuf[2][i] = s_aa;
            sbuf[3][i] = s_vv;
        }
    }
    __syncthreads();

    const long long S = (long long)B * (1 + NEG);
    float* dst = out_scores + (long long)b * (1 + NEG) + 1 + n0;
#pragma unroll
    for (int k = 0; k < 4; k++) {
        dst[k * S + threadIdx.x] = sbuf[k][threadIdx.x] / TEMPR;
    }
}

extern "C" void kernel_launch(void* const* d_in, const int* in_sizes, int n_in,
                              void* d_out, int out_size) {
    const float* audio_emb = (const float*)d_in[0];
    const float* video_emb = (const float*)d_in[1];
    const float* amem = (const float*)d_in[2];
    const float* vmem = (const float*)d_in[3];
    const void* indices = d_in[4];
    const void* negs = d_in[5];

    float* out = (float*)d_out;
    float* out_scores = out;                                    // [4,256,1025]
    float* out_amem = out + (size_t)4 * B * (1 + NEG);          // [300000,128]
    float* out_vmem = out_amem + (size_t)SAMPLES * D;           // [300000,128]

    // bulk copy of memories into output (dominant cost, ~614 MB of traffic)
    cudaMemcpyAsync(out_amem, amem, (size_t)SAMPLES * D * sizeof(float),
                    cudaMemcpyDeviceToDevice, 0);
    cudaMemcpyAsync(out_vmem, vmem, (size_t)SAMPLES * D * sizeof(float),
                    cudaMemcpyDeviceToDevice, 0);

    // normalize embeddings, positive scores, momentum scatter (after copy)
    prep_kernel<<<B, 128>>>(audio_emb, video_emb, amem, vmem, indices,
                            out_scores, out_amem, out_vmem);

    // negative scores
    dim3 grid(B, 2);
    score_kernel<<<grid, 512>>>(amem, vmem, indices, negs, out_scores);
}